// round 3
// baseline (speedup 1.0000x reference)
#include <cuda_runtime.h>
#include <cstdint>

#define FDIM 64
#define TWOF 128
#define NMAX 100000
#define BETA 0.5f
#define NEGSLOPE 0.01f

// Scratch: per-node projections P[n][0:64] = h[n]@W1^T, P[n][64:128] = h[n]@W2^T + b
// 16B-aligned: accessed via float4 (LDG.128/STG.128).
static __device__ __align__(16) float g_P[(size_t)NMAX * TWOF];
static __device__ __align__(16) float g_colsum[FDIM];
static __device__ __align__(16) float g_inv[FDIM];
static __device__ unsigned g_mm[4];  // enc(amin), enc(amax), enc(cmin), enc(cmax)

// Order-preserving float<->uint encoding so unsigned atomicMin/Max work for any sign.
__device__ __forceinline__ unsigned encf(float f) {
    unsigned u = __float_as_uint(f);
    return (u & 0x80000000u) ? ~u : (u | 0x80000000u);
}
__device__ __forceinline__ float decf(unsigned u) {
    return (u & 0x80000000u) ? __uint_as_float(u & 0x7FFFFFFFu) : __uint_as_float(~u);
}

__global__ void k_init() {
    int t = threadIdx.x;
    if (t < FDIM) g_colsum[t] = 0.0f;
    if (t == 0) {
        g_mm[0] = 0xFFFFFFFFu;  // amin (unsigned min)
        g_mm[1] = 0u;           // amax (unsigned max)
        g_mm[2] = 0xFFFFFFFFu;  // cmin
        g_mm[3] = 0u;           // cmax
    }
}

__global__ void k_minmax(const float* __restrict__ amount,
                         const float* __restrict__ count, int E) {
    int stride = gridDim.x * blockDim.x;
    int i0 = blockIdx.x * blockDim.x + threadIdx.x;
    float amin = INFINITY, amax = -INFINITY, cmin = INFINITY, cmax = -INFINITY;
    int E4 = E >> 2;
    const float4* a4 = (const float4*)amount;
    const float4* c4 = (const float4*)count;
    for (int i = i0; i < E4; i += stride) {
        float4 a = a4[i], c = c4[i];
        amin = fminf(amin, fminf(fminf(a.x, a.y), fminf(a.z, a.w)));
        amax = fmaxf(amax, fmaxf(fmaxf(a.x, a.y), fmaxf(a.z, a.w)));
        cmin = fminf(cmin, fminf(fminf(c.x, c.y), fminf(c.z, c.w)));
        cmax = fmaxf(cmax, fmaxf(fmaxf(c.x, c.y), fmaxf(c.z, c.w)));
    }
    for (int i = (E4 << 2) + i0; i < E; i += stride) {
        float a = amount[i], c = count[i];
        amin = fminf(amin, a); amax = fmaxf(amax, a);
        cmin = fminf(cmin, c); cmax = fmaxf(cmax, c);
    }
    #pragma unroll
    for (int off = 16; off; off >>= 1) {
        amin = fminf(amin, __shfl_down_sync(0xFFFFFFFFu, amin, off));
        amax = fmaxf(amax, __shfl_down_sync(0xFFFFFFFFu, amax, off));
        cmin = fminf(cmin, __shfl_down_sync(0xFFFFFFFFu, cmin, off));
        cmax = fmaxf(cmax, __shfl_down_sync(0xFFFFFFFFu, cmax, off));
    }
    if ((threadIdx.x & 31) == 0) {
        atomicMin(&g_mm[0], encf(amin));
        atomicMax(&g_mm[1], encf(amax));
        atomicMin(&g_mm[2], encf(cmin));
        atomicMax(&g_mm[3], encf(cmax));
    }
}

// Per-node projection GEMM: P[n][c] = sum_k h[n][k] * Wt[c][k] (+ bias for c>=64)
// Wt[c][k] = fc_w[c*128 + k] for c<64 ; fc_w[(c-64)*128 + 64 + k] for c>=64.
#define BN 32
__global__ void __launch_bounds__(256) k_gemm(const float* __restrict__ h,
                                              const float* __restrict__ fc_w,
                                              const float* __restrict__ fc_b, int N) {
    __shared__ __align__(16) float hs[BN][68];      // padded: conflict-free
    __shared__ __align__(16) float ws[FDIM][TWOF];  // ws[k][c]
    int n0 = blockIdx.x * BN;
    int tid = threadIdx.x;

    for (int idx = tid; idx < BN * FDIM; idx += 256) {
        int n = idx >> 6, k = idx & 63;
        int gn = n0 + n;
        hs[n][k] = (gn < N) ? h[gn * FDIM + k] : 0.0f;
    }
    for (int idx = tid; idx < FDIM * TWOF; idx += 256) {
        int k = idx >> 7, c = idx & 127;
        ws[k][c] = (c < FDIM) ? fc_w[c * TWOF + k]
                              : fc_w[(c - FDIM) * TWOF + FDIM + k];
    }
    __syncthreads();

    int tx = tid & 15, ty = tid >> 4;
    int c0 = tx * 8;       // 8 output cols, fully inside one half (64 % 8 == 0)
    int nl0 = ty * 2;      // 2 nodes
    float acc[2][8];
    #pragma unroll
    for (int i = 0; i < 2; i++)
        #pragma unroll
        for (int j = 0; j < 8; j++) acc[i][j] = 0.0f;

    #pragma unroll 8
    for (int k = 0; k < FDIM; k++) {
        float a0 = hs[nl0][k];
        float a1 = hs[nl0 + 1][k];
        float4 b0 = *(const float4*)&ws[k][c0];
        float4 b1 = *(const float4*)&ws[k][c0 + 4];
        acc[0][0] += a0 * b0.x; acc[0][1] += a0 * b0.y;
        acc[0][2] += a0 * b0.z; acc[0][3] += a0 * b0.w;
        acc[0][4] += a0 * b1.x; acc[0][5] += a0 * b1.y;
        acc[0][6] += a0 * b1.z; acc[0][7] += a0 * b1.w;
        acc[1][0] += a1 * b0.x; acc[1][1] += a1 * b0.y;
        acc[1][2] += a1 * b0.z; acc[1][3] += a1 * b0.w;
        acc[1][4] += a1 * b1.x; acc[1][5] += a1 * b1.y;
        acc[1][6] += a1 * b1.z; acc[1][7] += a1 * b1.w;
    }

    float bias[8];
    #pragma unroll
    for (int j = 0; j < 8; j++)
        bias[j] = (c0 >= FDIM) ? fc_b[c0 + j - FDIM] : 0.0f;

    #pragma unroll
    for (int i = 0; i < 2; i++) {
        int gn = n0 + nl0 + i;
        if (gn >= N) continue;
        float4 o0, o1;
        o0.x = acc[i][0] + bias[0]; o0.y = acc[i][1] + bias[1];
        o0.z = acc[i][2] + bias[2]; o0.w = acc[i][3] + bias[3];
        o1.x = acc[i][4] + bias[4]; o1.y = acc[i][5] + bias[5];
        o1.z = acc[i][6] + bias[6]; o1.w = acc[i][7] + bias[7];
        float* p = g_P + (size_t)gn * TWOF + c0;
        *(float4*)p = o0;
        *(float4*)(p + 4) = o1;
    }
}

// Pass 1: column sums of exp(leaky(P1[src]+P2[dst]) * ew). 16 lanes/edge, 4 cols/lane.
// adj is INT32: src = adj[0..E), dst = adj[E..2E)  (JAX x64 disabled -> int32).
__global__ void __launch_bounds__(256) k_pass1(const float* __restrict__ amount,
                                               const float* __restrict__ count,
                                               const int* __restrict__ adj, int E) {
    const int* srcA = adj;
    const int* dstA = adj + E;
    int lane16 = threadIdx.x & 15;
    int egrp = threadIdx.x >> 4;

    float amin = decf(g_mm[0]), amax = decf(g_mm[1]);
    float cmin = decf(g_mm[2]), cmax = decf(g_mm[3]);
    float as = BETA / (amax - amin + 1e-8f);
    float cs = (1.0f - BETA) / (cmax - cmin + 1e-8f);

    float4 acc = make_float4(0.f, 0.f, 0.f, 0.f);
    int co = lane16 * 4;

    for (int e = blockIdx.x * 16 + egrp; e < E; e += gridDim.x * 16) {
        int s = srcA[e];
        int d = dstA[e];
        float ew = (amount[e] - amin) * as + (count[e] - cmin) * cs;
        float4 p1 = *(const float4*)(g_P + (size_t)s * TWOF + co);
        float4 p2 = *(const float4*)(g_P + (size_t)d * TWOF + FDIM + co);
        float sx = p1.x + p2.x, sy = p1.y + p2.y, sz = p1.z + p2.z, sw = p1.w + p2.w;
        sx = (sx >= 0.f ? sx : NEGSLOPE * sx) * ew;
        sy = (sy >= 0.f ? sy : NEGSLOPE * sy) * ew;
        sz = (sz >= 0.f ? sz : NEGSLOPE * sz) * ew;
        sw = (sw >= 0.f ? sw : NEGSLOPE * sw) * ew;
        acc.x += __expf(sx);
        acc.y += __expf(sy);
        acc.z += __expf(sz);
        acc.w += __expf(sw);
    }

    __shared__ float scol[FDIM];
    if (threadIdx.x < FDIM) scol[threadIdx.x] = 0.0f;
    __syncthreads();
    atomicAdd(&scol[co + 0], acc.x);
    atomicAdd(&scol[co + 1], acc.y);
    atomicAdd(&scol[co + 2], acc.z);
    atomicAdd(&scol[co + 3], acc.w);
    __syncthreads();
    if (threadIdx.x < FDIM) atomicAdd(&g_colsum[threadIdx.x], scol[threadIdx.x]);
}

__global__ void k_inv() {
    int t = threadIdx.x;
    if (t < FDIM) g_inv[t] = 1.0f / g_colsum[t];
}

__device__ __forceinline__ void red_add_v4(float* p, float x, float y, float z, float w) {
    asm volatile("red.global.add.v4.f32 [%0], {%1, %2, %3, %4};"
                 :: "l"(p), "f"(x), "f"(y), "f"(z), "f"(w) : "memory");
}

// Pass 2: recompute exp-score, normalize by colsum, scatter att * h[dst] into out[src].
__global__ void __launch_bounds__(256) k_pass2(const float* __restrict__ amount,
                                               const float* __restrict__ count,
                                               const int* __restrict__ adj,
                                               const float* __restrict__ h,
                                               float* __restrict__ out, int E) {
    const int* srcA = adj;
    const int* dstA = adj + E;
    int lane16 = threadIdx.x & 15;
    int egrp = threadIdx.x >> 4;
    int co = lane16 * 4;

    float amin = decf(g_mm[0]), amax = decf(g_mm[1]);
    float cmin = decf(g_mm[2]), cmax = decf(g_mm[3]);
    float as = BETA / (amax - amin + 1e-8f);
    float cs = (1.0f - BETA) / (cmax - cmin + 1e-8f);
    float4 inv = *(const float4*)(g_inv + co);

    for (int e = blockIdx.x * 16 + egrp; e < E; e += gridDim.x * 16) {
        int s = srcA[e];
        int d = dstA[e];
        float ew = (amount[e] - amin) * as + (count[e] - cmin) * cs;
        float4 p1 = *(const float4*)(g_P + (size_t)s * TWOF + co);
        float4 p2 = *(const float4*)(g_P + (size_t)d * TWOF + FDIM + co);
        float sx = p1.x + p2.x, sy = p1.y + p2.y, sz = p1.z + p2.z, sw = p1.w + p2.w;
        sx = (sx >= 0.f ? sx : NEGSLOPE * sx) * ew;
        sy = (sy >= 0.f ? sy : NEGSLOPE * sy) * ew;
        sz = (sz >= 0.f ? sz : NEGSLOPE * sz) * ew;
        sw = (sw >= 0.f ? sw : NEGSLOPE * sw) * ew;
        float4 hv = *(const float4*)(h + (size_t)d * FDIM + co);
        float vx = __expf(sx) * inv.x * hv.x;
        float vy = __expf(sy) * inv.y * hv.y;
        float vz = __expf(sz) * inv.z * hv.z;
        float vw = __expf(sw) * inv.w * hv.w;
        red_add_v4(out + (size_t)s * FDIM + co, vx, vy, vz, vw);
    }
}

extern "C" void kernel_launch(void* const* d_in, const int* in_sizes, int n_in,
                              void* d_out, int out_size) {
    const float* h = (const float*)d_in[0];
    const int* adj = (const int*)d_in[1];      // int32! (JAX default x64-disabled)
    const float* amount = (const float*)d_in[2];
    const float* count = (const float*)d_in[3];
    const float* fc_w = (const float*)d_in[4];
    const float* fc_b = (const float*)d_in[5];
    float* out = (float*)d_out;

    int N = in_sizes[0] / FDIM;
    int E = in_sizes[2];

    k_init<<<1, 64>>>();
    cudaMemsetAsync(d_out, 0, (size_t)out_size * sizeof(float));
    k_minmax<<<512, 256>>>(amount, count, E);
    k_gemm<<<(N + BN - 1) / BN, 256>>>(h, fc_w, fc_b, N);
    k_pass1<<<1184, 256>>>(amount, count, adj, E);
    k_inv<<<1, 64>>>();
    k_pass2<<<1184, 256>>>(amount, count, adj, h, out, E);
}

// round 4
// speedup vs baseline: 1.2316x; 1.2316x over previous
#include <cuda_runtime.h>
#include <cstdint>

#define FDIM 64
#define TWOF 128
#define NMAX 100000
#define BETA 0.5f
#define NEGSLOPE 0.01f

// Scratch: per-node projections P[n][0:64] = h[n]@W1^T, P[n][64:128] = h[n]@W2^T + b
static __device__ __align__(16) float g_P[(size_t)NMAX * TWOF];
static __device__ __align__(16) float g_colsum[FDIM];
static __device__ __align__(16) float g_inv[FDIM];
static __device__ unsigned g_mm[4];  // enc(amin), enc(amax), enc(cmin), enc(cmax)

__device__ __forceinline__ unsigned encf(float f) {
    unsigned u = __float_as_uint(f);
    return (u & 0x80000000u) ? ~u : (u | 0x80000000u);
}
__device__ __forceinline__ float decf(unsigned u) {
    return (u & 0x80000000u) ? __uint_as_float(u & 0x7FFFFFFFu) : __uint_as_float(~u);
}

__global__ void k_init() {
    int t = threadIdx.x;
    if (t < FDIM) g_colsum[t] = 0.0f;
    if (t == 0) {
        g_mm[0] = 0xFFFFFFFFu;
        g_mm[1] = 0u;
        g_mm[2] = 0xFFFFFFFFu;
        g_mm[3] = 0u;
    }
}

__global__ void k_minmax(const float* __restrict__ amount,
                         const float* __restrict__ count, int E) {
    int stride = gridDim.x * blockDim.x;
    int i0 = blockIdx.x * blockDim.x + threadIdx.x;
    float amin = INFINITY, amax = -INFINITY, cmin = INFINITY, cmax = -INFINITY;
    int E4 = E >> 2;
    const float4* a4 = (const float4*)amount;
    const float4* c4 = (const float4*)count;
    for (int i = i0; i < E4; i += stride) {
        float4 a = a4[i], c = c4[i];
        amin = fminf(amin, fminf(fminf(a.x, a.y), fminf(a.z, a.w)));
        amax = fmaxf(amax, fmaxf(fmaxf(a.x, a.y), fmaxf(a.z, a.w)));
        cmin = fminf(cmin, fminf(fminf(c.x, c.y), fminf(c.z, c.w)));
        cmax = fmaxf(cmax, fmaxf(fmaxf(c.x, c.y), fmaxf(c.z, c.w)));
    }
    for (int i = (E4 << 2) + i0; i < E; i += stride) {
        float a = amount[i], c = count[i];
        amin = fminf(amin, a); amax = fmaxf(amax, a);
        cmin = fminf(cmin, c); cmax = fmaxf(cmax, c);
    }
    #pragma unroll
    for (int off = 16; off; off >>= 1) {
        amin = fminf(amin, __shfl_down_sync(0xFFFFFFFFu, amin, off));
        amax = fmaxf(amax, __shfl_down_sync(0xFFFFFFFFu, amax, off));
        cmin = fminf(cmin, __shfl_down_sync(0xFFFFFFFFu, cmin, off));
        cmax = fmaxf(cmax, __shfl_down_sync(0xFFFFFFFFu, cmax, off));
    }
    if ((threadIdx.x & 31) == 0) {
        atomicMin(&g_mm[0], encf(amin));
        atomicMax(&g_mm[1], encf(amax));
        atomicMin(&g_mm[2], encf(cmin));
        atomicMax(&g_mm[3], encf(cmax));
    }
}

// Per-node projection GEMM: P[n][c] = sum_k h[n][k] * Wt[c][k] (+ bias for c>=64)
#define BN 32
__global__ void __launch_bounds__(256) k_gemm(const float* __restrict__ h,
                                              const float* __restrict__ fc_w,
                                              const float* __restrict__ fc_b, int N) {
    __shared__ __align__(16) float hs[BN][68];
    __shared__ __align__(16) float ws[FDIM][TWOF];
    int n0 = blockIdx.x * BN;
    int tid = threadIdx.x;

    for (int idx = tid; idx < BN * FDIM; idx += 256) {
        int n = idx >> 6, k = idx & 63;
        int gn = n0 + n;
        hs[n][k] = (gn < N) ? h[gn * FDIM + k] : 0.0f;
    }
    for (int idx = tid; idx < FDIM * TWOF; idx += 256) {
        int k = idx >> 7, c = idx & 127;
        ws[k][c] = (c < FDIM) ? fc_w[c * TWOF + k]
                              : fc_w[(c - FDIM) * TWOF + FDIM + k];
    }
    __syncthreads();

    int tx = tid & 15, ty = tid >> 4;
    int c0 = tx * 8;
    int nl0 = ty * 2;
    float acc[2][8];
    #pragma unroll
    for (int i = 0; i < 2; i++)
        #pragma unroll
        for (int j = 0; j < 8; j++) acc[i][j] = 0.0f;

    #pragma unroll 8
    for (int k = 0; k < FDIM; k++) {
        float a0 = hs[nl0][k];
        float a1 = hs[nl0 + 1][k];
        float4 b0 = *(const float4*)&ws[k][c0];
        float4 b1 = *(const float4*)&ws[k][c0 + 4];
        acc[0][0] += a0 * b0.x; acc[0][1] += a0 * b0.y;
        acc[0][2] += a0 * b0.z; acc[0][3] += a0 * b0.w;
        acc[0][4] += a0 * b1.x; acc[0][5] += a0 * b1.y;
        acc[0][6] += a0 * b1.z; acc[0][7] += a0 * b1.w;
        acc[1][0] += a1 * b0.x; acc[1][1] += a1 * b0.y;
        acc[1][2] += a1 * b0.z; acc[1][3] += a1 * b0.w;
        acc[1][4] += a1 * b1.x; acc[1][5] += a1 * b1.y;
        acc[1][6] += a1 * b1.z; acc[1][7] += a1 * b1.w;
    }

    float bias[8];
    #pragma unroll
    for (int j = 0; j < 8; j++)
        bias[j] = (c0 >= FDIM) ? fc_b[c0 + j - FDIM] : 0.0f;

    #pragma unroll
    for (int i = 0; i < 2; i++) {
        int gn = n0 + nl0 + i;
        if (gn >= N) continue;
        float4 o0, o1;
        o0.x = acc[i][0] + bias[0]; o0.y = acc[i][1] + bias[1];
        o0.z = acc[i][2] + bias[2]; o0.w = acc[i][3] + bias[3];
        o1.x = acc[i][4] + bias[4]; o1.y = acc[i][5] + bias[5];
        o1.z = acc[i][6] + bias[6]; o1.w = acc[i][7] + bias[7];
        float* p = g_P + (size_t)gn * TWOF + c0;
        *(float4*)p = o0;
        *(float4*)(p + 4) = o1;
    }
}

__device__ __forceinline__ void red_add_v4(float* p, float x, float y, float z, float w) {
    asm volatile("red.global.add.v4.f32 [%0], {%1, %2, %3, %4};"
                 :: "l"(p), "f"(x), "f"(y), "f"(z), "f"(w) : "memory");
}

// FUSED edge pass: one gather of P1[src]/P2[dst]/h[dst] per edge.
// Scatters UNNORMALIZED exp(score)*h[dst] into out[src] via RED.v4, and
// accumulates per-column exp sums (register -> smem -> global atomic).
// Normalization by 1/colsum[c] happens in k_norm afterward (it commutes).
__global__ void __launch_bounds__(256) k_edge(const float* __restrict__ amount,
                                              const float* __restrict__ count,
                                              const int* __restrict__ adj,
                                              const float* __restrict__ h,
                                              float* __restrict__ out, int E) {
    const int* srcA = adj;
    const int* dstA = adj + E;
    int lane16 = threadIdx.x & 15;
    int egrp = threadIdx.x >> 4;
    int co = lane16 * 4;

    float amin = decf(g_mm[0]), amax = decf(g_mm[1]);
    float cmin = decf(g_mm[2]), cmax = decf(g_mm[3]);
    float as = BETA / (amax - amin + 1e-8f);
    float cs = (1.0f - BETA) / (cmax - cmin + 1e-8f);

    float4 acc = make_float4(0.f, 0.f, 0.f, 0.f);

    for (int e = blockIdx.x * 16 + egrp; e < E; e += gridDim.x * 16) {
        int s = srcA[e];
        int d = dstA[e];
        float ew = (amount[e] - amin) * as + (count[e] - cmin) * cs;
        float4 p1 = *(const float4*)(g_P + (size_t)s * TWOF + co);
        float4 p2 = *(const float4*)(g_P + (size_t)d * TWOF + FDIM + co);
        float sx = p1.x + p2.x, sy = p1.y + p2.y, sz = p1.z + p2.z, sw = p1.w + p2.w;
        sx = (sx >= 0.f ? sx : NEGSLOPE * sx) * ew;
        sy = (sy >= 0.f ? sy : NEGSLOPE * sy) * ew;
        sz = (sz >= 0.f ? sz : NEGSLOPE * sz) * ew;
        sw = (sw >= 0.f ? sw : NEGSLOPE * sw) * ew;
        float ex = __expf(sx), ey = __expf(sy), ez = __expf(sz), ewv = __expf(sw);
        acc.x += ex; acc.y += ey; acc.z += ez; acc.w += ewv;
        float4 hv = *(const float4*)(h + (size_t)d * FDIM + co);
        red_add_v4(out + (size_t)s * FDIM + co,
                   ex * hv.x, ey * hv.y, ez * hv.z, ewv * hv.w);
    }

    __shared__ float scol[FDIM];
    if (threadIdx.x < FDIM) scol[threadIdx.x] = 0.0f;
    __syncthreads();
    atomicAdd(&scol[co + 0], acc.x);
    atomicAdd(&scol[co + 1], acc.y);
    atomicAdd(&scol[co + 2], acc.z);
    atomicAdd(&scol[co + 3], acc.w);
    __syncthreads();
    if (threadIdx.x < FDIM) atomicAdd(&g_colsum[threadIdx.x], scol[threadIdx.x]);
}

__global__ void k_inv() {
    int t = threadIdx.x;
    if (t < FDIM) g_inv[t] = 1.0f / g_colsum[t];
}

// Final column rescale: out[n][c] *= 1/colsum[c]
__global__ void __launch_bounds__(256) k_norm(float* __restrict__ out, int total4) {
    int i = blockIdx.x * blockDim.x + threadIdx.x;
    if (i >= total4) return;
    float4 inv = *(const float4*)(g_inv + (i & 15) * 4);
    float4 v = ((float4*)out)[i];
    v.x *= inv.x; v.y *= inv.y; v.z *= inv.z; v.w *= inv.w;
    ((float4*)out)[i] = v;
}

extern "C" void kernel_launch(void* const* d_in, const int* in_sizes, int n_in,
                              void* d_out, int out_size) {
    const float* h = (const float*)d_in[0];
    const int* adj = (const int*)d_in[1];      // int32 (JAX default x64-disabled)
    const float* amount = (const float*)d_in[2];
    const float* count = (const float*)d_in[3];
    const float* fc_w = (const float*)d_in[4];
    const float* fc_b = (const float*)d_in[5];
    float* out = (float*)d_out;

    int N = in_sizes[0] / FDIM;
    int E = in_sizes[2];

    k_init<<<1, 64>>>();
    cudaMemsetAsync(d_out, 0, (size_t)out_size * sizeof(float));
    k_minmax<<<512, 256>>>(amount, count, E);
    k_gemm<<<(N + BN - 1) / BN, 256>>>(h, fc_w, fc_b, N);
    k_edge<<<1184, 256>>>(amount, count, adj, h, out, E);
    k_inv<<<1, 64>>>();
    int total4 = out_size / 4;  // N*FDIM/4 float4s
    k_norm<<<(total4 + 255) / 256, 256>>>(out, total4);
}

// round 5
// speedup vs baseline: 1.4979x; 1.2162x over previous
#include <cuda_runtime.h>
#include <cstdint>

#define FDIM 64
#define TWOF 128
#define NMAX 100000
#define BETA 0.5f
#define NEGSLOPE 0.01f

static __device__ __align__(16) float g_P[(size_t)NMAX * TWOF];
static __device__ __align__(16) float g_Wt[FDIM * TWOF];   // [k][c] transposed weights
static __device__ __align__(16) float g_colsum[FDIM];
static __device__ __align__(16) float g_inv[FDIM];
static __device__ unsigned g_mm[4];

__device__ __forceinline__ unsigned encf(float f) {
    unsigned u = __float_as_uint(f);
    return (u & 0x80000000u) ? ~u : (u | 0x80000000u);
}
__device__ __forceinline__ float decf(unsigned u) {
    return (u & 0x80000000u) ? __uint_as_float(u & 0x7FFFFFFFu) : __uint_as_float(~u);
}

__global__ void k_init() {
    int t = threadIdx.x;
    if (t < FDIM) g_colsum[t] = 0.0f;
    if (t == 0) {
        g_mm[0] = 0xFFFFFFFFu;
        g_mm[1] = 0u;
        g_mm[2] = 0xFFFFFFFFu;
        g_mm[3] = 0u;
    }
}

// One-time weight transpose: g_Wt[k*128+c] = Wt[c][k]. 8192 elems, uncoalesced
// read ONCE (vs per-gemm-block before — that was the hidden ~100us).
__global__ void k_wprep(const float* __restrict__ fc_w) {
    int idx = blockIdx.x * 256 + threadIdx.x;
    if (idx >= FDIM * TWOF) return;
    int k = idx >> 7, c = idx & 127;
    g_Wt[idx] = (c < FDIM) ? fc_w[c * TWOF + k]
                           : fc_w[(c - FDIM) * TWOF + FDIM + k];
}

__global__ void k_minmax(const float* __restrict__ amount,
                         const float* __restrict__ count, int E) {
    int stride = gridDim.x * blockDim.x;
    int i0 = blockIdx.x * blockDim.x + threadIdx.x;
    float amin = INFINITY, amax = -INFINITY, cmin = INFINITY, cmax = -INFINITY;
    int E4 = E >> 2;
    const float4* a4 = (const float4*)amount;
    const float4* c4 = (const float4*)count;
    for (int i = i0; i < E4; i += stride) {
        float4 a = a4[i], c = c4[i];
        amin = fminf(amin, fminf(fminf(a.x, a.y), fminf(a.z, a.w)));
        amax = fmaxf(amax, fmaxf(fmaxf(a.x, a.y), fmaxf(a.z, a.w)));
        cmin = fminf(cmin, fminf(fminf(c.x, c.y), fminf(c.z, c.w)));
        cmax = fmaxf(cmax, fmaxf(fmaxf(c.x, c.y), fmaxf(c.z, c.w)));
    }
    for (int i = (E4 << 2) + i0; i < E; i += stride) {
        float a = amount[i], c = count[i];
        amin = fminf(amin, a); amax = fmaxf(amax, a);
        cmin = fminf(cmin, c); cmax = fmaxf(cmax, c);
    }
    #pragma unroll
    for (int off = 16; off; off >>= 1) {
        amin = fminf(amin, __shfl_down_sync(0xFFFFFFFFu, amin, off));
        amax = fmaxf(amax, __shfl_down_sync(0xFFFFFFFFu, amax, off));
        cmin = fminf(cmin, __shfl_down_sync(0xFFFFFFFFu, cmin, off));
        cmax = fmaxf(cmax, __shfl_down_sync(0xFFFFFFFFu, cmax, off));
    }
    if ((threadIdx.x & 31) == 0) {
        atomicMin(&g_mm[0], encf(amin));
        atomicMax(&g_mm[1], encf(amax));
        atomicMin(&g_mm[2], encf(cmin));
        atomicMax(&g_mm[3], encf(cmax));
    }
}

// Per-node projection GEMM: P[n][c] = sum_k h[n][k] * g_Wt[k][c] (+ bias c>=64)
#define BN 32
__global__ void __launch_bounds__(256) k_gemm(const float* __restrict__ h,
                                              const float* __restrict__ fc_b, int N) {
    __shared__ __align__(16) float hs[BN][68];
    __shared__ __align__(16) float ws[FDIM * TWOF];  // [k][c]
    int n0 = blockIdx.x * BN;
    int tid = threadIdx.x;

    for (int idx = tid; idx < BN * FDIM; idx += 256) {
        int n = idx >> 6, k = idx & 63;
        int gn = n0 + n;
        hs[n][k] = (gn < N) ? h[gn * FDIM + k] : 0.0f;
    }
    // coalesced float4 copy of pre-transposed weights
    {
        const float4* s4 = (const float4*)g_Wt;
        float4* d4 = (float4*)ws;
        #pragma unroll
        for (int idx = tid; idx < FDIM * TWOF / 4; idx += 256) d4[idx] = s4[idx];
    }
    __syncthreads();

    int tx = tid & 15, ty = tid >> 4;
    int c0 = tx * 8;
    int nl0 = ty * 2;
    float acc[2][8];
    #pragma unroll
    for (int i = 0; i < 2; i++)
        #pragma unroll
        for (int j = 0; j < 8; j++) acc[i][j] = 0.0f;

    #pragma unroll 8
    for (int k = 0; k < FDIM; k++) {
        float a0 = hs[nl0][k];
        float a1 = hs[nl0 + 1][k];
        float4 b0 = *(const float4*)&ws[k * TWOF + c0];
        float4 b1 = *(const float4*)&ws[k * TWOF + c0 + 4];
        acc[0][0] += a0 * b0.x; acc[0][1] += a0 * b0.y;
        acc[0][2] += a0 * b0.z; acc[0][3] += a0 * b0.w;
        acc[0][4] += a0 * b1.x; acc[0][5] += a0 * b1.y;
        acc[0][6] += a0 * b1.z; acc[0][7] += a0 * b1.w;
        acc[1][0] += a1 * b0.x; acc[1][1] += a1 * b0.y;
        acc[1][2] += a1 * b0.z; acc[1][3] += a1 * b0.w;
        acc[1][4] += a1 * b1.x; acc[1][5] += a1 * b1.y;
        acc[1][6] += a1 * b1.z; acc[1][7] += a1 * b1.w;
    }

    float bias[8];
    #pragma unroll
    for (int j = 0; j < 8; j++)
        bias[j] = (c0 >= FDIM) ? fc_b[c0 + j - FDIM] : 0.0f;

    #pragma unroll
    for (int i = 0; i < 2; i++) {
        int gn = n0 + nl0 + i;
        if (gn >= N) continue;
        float4 o0, o1;
        o0.x = acc[i][0] + bias[0]; o0.y = acc[i][1] + bias[1];
        o0.z = acc[i][2] + bias[2]; o0.w = acc[i][3] + bias[3];
        o1.x = acc[i][4] + bias[4]; o1.y = acc[i][5] + bias[5];
        o1.z = acc[i][6] + bias[6]; o1.w = acc[i][7] + bias[7];
        float* p = g_P + (size_t)gn * TWOF + c0;
        *(float4*)p = o0;
        *(float4*)(p + 4) = o1;
    }
}

// RED without memory clobber: results are never read inside this kernel, so the
// compiler may freely hoist the next iteration's gathers above it (MLP).
__device__ __forceinline__ void red_add_v4(float* p, float x, float y, float z, float w) {
    asm volatile("red.global.add.v4.f32 [%0], {%1, %2, %3, %4};"
                 :: "l"(p), "f"(x), "f"(y), "f"(z), "f"(w));
}

// FUSED edge pass, 2 edges per thread-iteration for independent gather chains.
__global__ void __launch_bounds__(256) k_edge(const float* __restrict__ amount,
                                              const float* __restrict__ count,
                                              const int* __restrict__ adj,
                                              const float* __restrict__ h,
                                              float* __restrict__ out, int E) {
    const int* srcA = adj;
    const int* dstA = adj + E;
    int lane16 = threadIdx.x & 15;
    int egrp = threadIdx.x >> 4;   // 0..15
    int co = lane16 * 4;

    float amin = decf(g_mm[0]), amax = decf(g_mm[1]);
    float cmin = decf(g_mm[2]), cmax = decf(g_mm[3]);
    float as = BETA / (amax - amin + 1e-8f);
    float cs = (1.0f - BETA) / (cmax - cmin + 1e-8f);

    float4 acc = make_float4(0.f, 0.f, 0.f, 0.f);

    int stride = gridDim.x * 32;
    for (int e0 = blockIdx.x * 32 + egrp * 2; e0 < E; e0 += stride) {
        int e1 = e0 + 1;
        bool has1 = (e1 < E);

        int s0 = srcA[e0];
        int d0 = dstA[e0];
        float ew0 = (amount[e0] - amin) * as + (count[e0] - cmin) * cs;
        int s1 = has1 ? srcA[e1] : s0;
        int d1 = has1 ? dstA[e1] : d0;
        float ew1 = has1 ? ((amount[e1] - amin) * as + (count[e1] - cmin) * cs) : 0.f;

        float4 p10 = *(const float4*)(g_P + (size_t)s0 * TWOF + co);
        float4 p20 = *(const float4*)(g_P + (size_t)d0 * TWOF + FDIM + co);
        float4 hv0 = *(const float4*)(h + (size_t)d0 * FDIM + co);
        float4 p11 = *(const float4*)(g_P + (size_t)s1 * TWOF + co);
        float4 p21 = *(const float4*)(g_P + (size_t)d1 * TWOF + FDIM + co);
        float4 hv1 = *(const float4*)(h + (size_t)d1 * FDIM + co);

        float sx = p10.x + p20.x, sy = p10.y + p20.y, sz = p10.z + p20.z, sw = p10.w + p20.w;
        sx = (sx >= 0.f ? sx : NEGSLOPE * sx) * ew0;
        sy = (sy >= 0.f ? sy : NEGSLOPE * sy) * ew0;
        sz = (sz >= 0.f ? sz : NEGSLOPE * sz) * ew0;
        sw = (sw >= 0.f ? sw : NEGSLOPE * sw) * ew0;
        float ex = __expf(sx), ey = __expf(sy), ez = __expf(sz), ew_ = __expf(sw);
        acc.x += ex; acc.y += ey; acc.z += ez; acc.w += ew_;
        red_add_v4(out + (size_t)s0 * FDIM + co,
                   ex * hv0.x, ey * hv0.y, ez * hv0.z, ew_ * hv0.w);

        if (has1) {
            float tx = p11.x + p21.x, ty = p11.y + p21.y, tz = p11.z + p21.z, tw = p11.w + p21.w;
            tx = (tx >= 0.f ? tx : NEGSLOPE * tx) * ew1;
            ty = (ty >= 0.f ? ty : NEGSLOPE * ty) * ew1;
            tz = (tz >= 0.f ? tz : NEGSLOPE * tz) * ew1;
            tw = (tw >= 0.f ? tw : NEGSLOPE * tw) * ew1;
            float fx = __expf(tx), fy = __expf(ty), fz = __expf(tz), fw = __expf(tw);
            acc.x += fx; acc.y += fy; acc.z += fz; acc.w += fw;
            red_add_v4(out + (size_t)s1 * FDIM + co,
                       fx * hv1.x, fy * hv1.y, fz * hv1.z, fw * hv1.w);
        }
    }

    __shared__ float scol[FDIM];
    if (threadIdx.x < FDIM) scol[threadIdx.x] = 0.0f;
    __syncthreads();
    atomicAdd(&scol[co + 0], acc.x);
    atomicAdd(&scol[co + 1], acc.y);
    atomicAdd(&scol[co + 2], acc.z);
    atomicAdd(&scol[co + 3], acc.w);
    __syncthreads();
    if (threadIdx.x < FDIM) atomicAdd(&g_colsum[threadIdx.x], scol[threadIdx.x]);
}

__global__ void k_inv() {
    int t = threadIdx.x;
    if (t < FDIM) g_inv[t] = 1.0f / g_colsum[t];
}

__global__ void __launch_bounds__(256) k_norm(float* __restrict__ out, int total4) {
    int i = blockIdx.x * blockDim.x + threadIdx.x;
    if (i >= total4) return;
    float4 inv = *(const float4*)(g_inv + (i & 15) * 4);
    float4 v = ((float4*)out)[i];
    v.x *= inv.x; v.y *= inv.y; v.z *= inv.z; v.w *= inv.w;
    ((float4*)out)[i] = v;
}

extern "C" void kernel_launch(void* const* d_in, const int* in_sizes, int n_in,
                              void* d_out, int out_size) {
    const float* h = (const float*)d_in[0];
    const int* adj = (const int*)d_in[1];
    const float* amount = (const float*)d_in[2];
    const float* count = (const float*)d_in[3];
    const float* fc_w = (const float*)d_in[4];
    const float* fc_b = (const float*)d_in[5];
    float* out = (float*)d_out;

    int N = in_sizes[0] / FDIM;
    int E = in_sizes[2];

    k_init<<<1, 64>>>();
    k_wprep<<<(FDIM * TWOF + 255) / 256, 256>>>(fc_w);
    cudaMemsetAsync(d_out, 0, (size_t)out_size * sizeof(float));
    k_minmax<<<512, 256>>>(amount, count, E);
    k_gemm<<<(N + BN - 1) / BN, 256>>>(h, fc_b, N);
    k_edge<<<1184, 256>>>(amount, count, adj, h, out, E);
    k_inv<<<1, 64>>>();
    int total4 = out_size / 4;
    k_norm<<<(total4 + 255) / 256, 256>>>(out, total4);
}

// round 6
// speedup vs baseline: 2.1419x; 1.4299x over previous
#include <cuda_runtime.h>
#include <cstdint>

#define FDIM 64
#define TWOF 128
#define NMAX 100000
#define BETA 0.5f
#define NEGSLOPE 0.01f

static __device__ __align__(16) float g_P[(size_t)NMAX * TWOF];
static __device__ __align__(16) float g_Wt[FDIM * TWOF];   // [k][c] transposed weights
static __device__ __align__(16) float g_colsum[FDIM];
static __device__ __align__(16) float g_inv[FDIM];
static __device__ unsigned g_mm[4];

__device__ __forceinline__ unsigned encf(float f) {
    unsigned u = __float_as_uint(f);
    return (u & 0x80000000u) ? ~u : (u | 0x80000000u);
}
__device__ __forceinline__ float decf(unsigned u) {
    return (u & 0x80000000u) ? __uint_as_float(u & 0x7FFFFFFFu) : __uint_as_float(~u);
}

// packed f32x2 fma: d = a*b + d  (FFMA2 in SASS; only reachable via PTX)
__device__ __forceinline__ void ffma2(unsigned long long& d, unsigned long long a,
                                      unsigned long long b) {
    asm("fma.rn.f32x2 %0, %1, %2, %3;" : "=l"(d) : "l"(a), "l"(b), "l"(d));
}
__device__ __forceinline__ unsigned long long dup2(float x) {
    unsigned long long d;
    unsigned u = __float_as_uint(x);
    asm("mov.b64 %0, {%1, %1};" : "=l"(d) : "r"(u));
    return d;
}
__device__ __forceinline__ void unpack2(unsigned long long v, float& lo, float& hi) {
    unsigned a, b;
    asm("mov.b64 {%0, %1}, %2;" : "=r"(a), "=r"(b) : "l"(v));
    lo = __uint_as_float(a);
    hi = __uint_as_float(b);
}

__global__ void k_init() {
    int t = threadIdx.x;
    if (t < FDIM) g_colsum[t] = 0.0f;
    if (t == 0) {
        g_mm[0] = 0xFFFFFFFFu;
        g_mm[1] = 0u;
        g_mm[2] = 0xFFFFFFFFu;
        g_mm[3] = 0u;
    }
}

// One-time weight transpose: g_Wt[k*128+c] = Wt[c][k].
__global__ void k_wprep(const float* __restrict__ fc_w) {
    int idx = blockIdx.x * 256 + threadIdx.x;
    if (idx >= FDIM * TWOF) return;
    int k = idx >> 7, c = idx & 127;
    g_Wt[idx] = (c < FDIM) ? fc_w[c * TWOF + k]
                           : fc_w[(c - FDIM) * TWOF + FDIM + k];
}

__global__ void k_minmax(const float* __restrict__ amount,
                         const float* __restrict__ count, int E) {
    int stride = gridDim.x * blockDim.x;
    int i0 = blockIdx.x * blockDim.x + threadIdx.x;
    float amin = INFINITY, amax = -INFINITY, cmin = INFINITY, cmax = -INFINITY;
    int E4 = E >> 2;
    const float4* a4 = (const float4*)amount;
    const float4* c4 = (const float4*)count;
    for (int i = i0; i < E4; i += stride) {
        float4 a = a4[i], c = c4[i];
        amin = fminf(amin, fminf(fminf(a.x, a.y), fminf(a.z, a.w)));
        amax = fmaxf(amax, fmaxf(fmaxf(a.x, a.y), fmaxf(a.z, a.w)));
        cmin = fminf(cmin, fminf(fminf(c.x, c.y), fminf(c.z, c.w)));
        cmax = fmaxf(cmax, fmaxf(fmaxf(c.x, c.y), fmaxf(c.z, c.w)));
    }
    for (int i = (E4 << 2) + i0; i < E; i += stride) {
        float a = amount[i], c = count[i];
        amin = fminf(amin, a); amax = fmaxf(amax, a);
        cmin = fminf(cmin, c); cmax = fmaxf(cmax, c);
    }
    #pragma unroll
    for (int off = 16; off; off >>= 1) {
        amin = fminf(amin, __shfl_down_sync(0xFFFFFFFFu, amin, off));
        amax = fmaxf(amax, __shfl_down_sync(0xFFFFFFFFu, amax, off));
        cmin = fminf(cmin, __shfl_down_sync(0xFFFFFFFFu, cmin, off));
        cmax = fmaxf(cmax, __shfl_down_sync(0xFFFFFFFFu, cmax, off));
    }
    if ((threadIdx.x & 31) == 0) {
        atomicMin(&g_mm[0], encf(amin));
        atomicMax(&g_mm[1], encf(amax));
        atomicMin(&g_mm[2], encf(cmin));
        atomicMax(&g_mm[3], encf(cmax));
    }
}

// Per-node projection GEMM, FFMA2 version.
// 64 nodes/block, 128 threads: tx(0..15) -> 8 cols, ty(0..7) -> 8 nodes.
// B read straight from g_Wt via LDG.128 (32KB, L1-resident; no smem staging).
#define GN 64
__global__ void __launch_bounds__(128) k_gemm(const float* __restrict__ h,
                                              const float* __restrict__ fc_b, int N) {
    __shared__ __align__(16) float hs[GN][68];   // 17.4KB, 16B-aligned rows
    int n0 = blockIdx.x * GN;
    int tid = threadIdx.x;

    // stage h rows coalesced (float4 along k)
    {
        const float4* h4 = (const float4*)h;
        for (int idx = tid; idx < GN * (FDIM / 4); idx += 128) {
            int n = idx >> 4, kq = idx & 15;
            int gn = n0 + n;
            float4 v = (gn < N) ? h4[(size_t)gn * (FDIM / 4) + kq]
                                : make_float4(0.f, 0.f, 0.f, 0.f);
            *(float4*)&hs[n][kq * 4] = v;
        }
    }
    __syncthreads();

    int tx = tid & 15, ty = tid >> 4;
    int c0 = tx * 8;
    int nb = ty * 8;

    unsigned long long acc[8][4];
    #pragma unroll
    for (int i = 0; i < 8; i++)
        #pragma unroll
        for (int j = 0; j < 4; j++) acc[i][j] = 0ull;

    #pragma unroll 4
    for (int k = 0; k < FDIM; k++) {
        const ulonglong2* bp = (const ulonglong2*)(g_Wt + k * TWOF + c0);
        ulonglong2 b01 = __ldg(bp);
        ulonglong2 b23 = __ldg(bp + 1);
        #pragma unroll
        for (int i = 0; i < 8; i++) {
            unsigned long long a2 = dup2(hs[nb + i][k]);
            ffma2(acc[i][0], a2, b01.x);
            ffma2(acc[i][1], a2, b01.y);
            ffma2(acc[i][2], a2, b23.x);
            ffma2(acc[i][3], a2, b23.y);
        }
    }

    float bias[8];
    #pragma unroll
    for (int j = 0; j < 8; j++)
        bias[j] = (c0 >= FDIM) ? __ldg(&fc_b[c0 + j - FDIM]) : 0.0f;

    #pragma unroll
    for (int i = 0; i < 8; i++) {
        int gn = n0 + nb + i;
        if (gn >= N) continue;
        float o[8];
        #pragma unroll
        for (int j = 0; j < 4; j++) unpack2(acc[i][j], o[2 * j], o[2 * j + 1]);
        float4 o0 = make_float4(o[0] + bias[0], o[1] + bias[1], o[2] + bias[2], o[3] + bias[3]);
        float4 o1 = make_float4(o[4] + bias[4], o[5] + bias[5], o[6] + bias[6], o[7] + bias[7]);
        float* p = g_P + (size_t)gn * TWOF + c0;
        *(float4*)p = o0;
        *(float4*)(p + 4) = o1;
    }
}

// RED without memory clobber: compiler may hoist later gathers above it.
__device__ __forceinline__ void red_add_v4(float* p, float x, float y, float z, float w) {
    asm volatile("red.global.add.v4.f32 [%0], {%1, %2, %3, %4};"
                 :: "l"(p), "f"(x), "f"(y), "f"(z), "f"(w));
}

__device__ __forceinline__ float lrelu_ew(float s, float ew) {
    return (s >= 0.f ? s : NEGSLOPE * s) * ew;
}

// FUSED edge pass, 4 edges per 16-lane group per iteration (12 gathers in flight).
__global__ void __launch_bounds__(256) k_edge(const float* __restrict__ amount,
                                              const float* __restrict__ count,
                                              const int* __restrict__ adj,
                                              const float* __restrict__ h,
                                              float* __restrict__ out, int E) {
    const int* srcA = adj;
    const int* dstA = adj + E;
    int lane16 = threadIdx.x & 15;
    int egrp = threadIdx.x >> 4;
    int co = lane16 * 4;

    float amin = decf(g_mm[0]), amax = decf(g_mm[1]);
    float cmin = decf(g_mm[2]), cmax = decf(g_mm[3]);
    float as = BETA / (amax - amin + 1e-8f);
    float cs = (1.0f - BETA) / (cmax - cmin + 1e-8f);

    float4 acc = make_float4(0.f, 0.f, 0.f, 0.f);

    int g0 = blockIdx.x * 16 + egrp;
    int gstride = gridDim.x * 16;
    int E4 = E >> 2;  // vectorized groups of 4

    for (int g = g0; g < E4; g += gstride) {
        int e0 = g * 4;
        int4 s4 = *(const int4*)(srcA + e0);
        int4 d4 = *(const int4*)(dstA + e0);
        float4 am = *(const float4*)(amount + e0);
        float4 ct = *(const float4*)(count + e0);

        // all 12 gathers issued before any consume
        float4 p1a = *(const float4*)(g_P + (size_t)s4.x * TWOF + co);
        float4 p1b = *(const float4*)(g_P + (size_t)s4.y * TWOF + co);
        float4 p1c = *(const float4*)(g_P + (size_t)s4.z * TWOF + co);
        float4 p1d = *(const float4*)(g_P + (size_t)s4.w * TWOF + co);
        float4 p2a = *(const float4*)(g_P + (size_t)d4.x * TWOF + FDIM + co);
        float4 p2b = *(const float4*)(g_P + (size_t)d4.y * TWOF + FDIM + co);
        float4 p2c = *(const float4*)(g_P + (size_t)d4.z * TWOF + FDIM + co);
        float4 p2d = *(const float4*)(g_P + (size_t)d4.w * TWOF + FDIM + co);
        float4 hva = *(const float4*)(h + (size_t)d4.x * FDIM + co);
        float4 hvb = *(const float4*)(h + (size_t)d4.y * FDIM + co);
        float4 hvc = *(const float4*)(h + (size_t)d4.z * FDIM + co);
        float4 hvd = *(const float4*)(h + (size_t)d4.w * FDIM + co);

        float ew0 = (am.x - amin) * as + (ct.x - cmin) * cs;
        float ew1 = (am.y - amin) * as + (ct.y - cmin) * cs;
        float ew2 = (am.z - amin) * as + (ct.z - cmin) * cs;
        float ew3 = (am.w - amin) * as + (ct.w - cmin) * cs;

        {
            float ex = __expf(lrelu_ew(p1a.x + p2a.x, ew0));
            float ey = __expf(lrelu_ew(p1a.y + p2a.y, ew0));
            float ez = __expf(lrelu_ew(p1a.z + p2a.z, ew0));
            float ew_ = __expf(lrelu_ew(p1a.w + p2a.w, ew0));
            acc.x += ex; acc.y += ey; acc.z += ez; acc.w += ew_;
            red_add_v4(out + (size_t)s4.x * FDIM + co,
                       ex * hva.x, ey * hva.y, ez * hva.z, ew_ * hva.w);
        }
        {
            float ex = __expf(lrelu_ew(p1b.x + p2b.x, ew1));
            float ey = __expf(lrelu_ew(p1b.y + p2b.y, ew1));
            float ez = __expf(lrelu_ew(p1b.z + p2b.z, ew1));
            float ew_ = __expf(lrelu_ew(p1b.w + p2b.w, ew1));
            acc.x += ex; acc.y += ey; acc.z += ez; acc.w += ew_;
            red_add_v4(out + (size_t)s4.y * FDIM + co,
                       ex * hvb.x, ey * hvb.y, ez * hvb.z, ew_ * hvb.w);
        }
        {
            float ex = __expf(lrelu_ew(p1c.x + p2c.x, ew2));
            float ey = __expf(lrelu_ew(p1c.y + p2c.y, ew2));
            float ez = __expf(lrelu_ew(p1c.z + p2c.z, ew2));
            float ew_ = __expf(lrelu_ew(p1c.w + p2c.w, ew2));
            acc.x += ex; acc.y += ey; acc.z += ez; acc.w += ew_;
            red_add_v4(out + (size_t)s4.z * FDIM + co,
                       ex * hvc.x, ey * hvc.y, ez * hvc.z, ew_ * hvc.w);
        }
        {
            float ex = __expf(lrelu_ew(p1d.x + p2d.x, ew3));
            float ey = __expf(lrelu_ew(p1d.y + p2d.y, ew3));
            float ez = __expf(lrelu_ew(p1d.z + p2d.z, ew3));
            float ew_ = __expf(lrelu_ew(p1d.w + p2d.w, ew3));
            acc.x += ex; acc.y += ey; acc.z += ez; acc.w += ew_;
            red_add_v4(out + (size_t)s4.w * FDIM + co,
                       ex * hvd.x, ey * hvd.y, ez * hvd.z, ew_ * hvd.w);
        }
    }

    // tail (E % 4), handled by one group
    if (blockIdx.x == 0 && egrp == 0) {
        for (int e = E & ~3; e < E; e++) {
            int s = srcA[e], d = dstA[e];
            float ew = (amount[e] - amin) * as + (count[e] - cmin) * cs;
            float4 p1 = *(const float4*)(g_P + (size_t)s * TWOF + co);
            float4 p2 = *(const float4*)(g_P + (size_t)d * TWOF + FDIM + co);
            float4 hv = *(const float4*)(h + (size_t)d * FDIM + co);
            float ex = __expf(lrelu_ew(p1.x + p2.x, ew));
            float ey = __expf(lrelu_ew(p1.y + p2.y, ew));
            float ez = __expf(lrelu_ew(p1.z + p2.z, ew));
            float ew_ = __expf(lrelu_ew(p1.w + p2.w, ew));
            acc.x += ex; acc.y += ey; acc.z += ez; acc.w += ew_;
            red_add_v4(out + (size_t)s * FDIM + co,
                       ex * hv.x, ey * hv.y, ez * hv.z, ew_ * hv.w);
        }
    }

    __shared__ float scol[FDIM];
    if (threadIdx.x < FDIM) scol[threadIdx.x] = 0.0f;
    __syncthreads();
    atomicAdd(&scol[co + 0], acc.x);
    atomicAdd(&scol[co + 1], acc.y);
    atomicAdd(&scol[co + 2], acc.z);
    atomicAdd(&scol[co + 3], acc.w);
    __syncthreads();
    if (threadIdx.x < FDIM) atomicAdd(&g_colsum[threadIdx.x], scol[threadIdx.x]);
}

__global__ void k_inv() {
    int t = threadIdx.x;
    if (t < FDIM) g_inv[t] = 1.0f / g_colsum[t];
}

__global__ void __launch_bounds__(256) k_norm(float* __restrict__ out, int total4) {
    int i = blockIdx.x * blockDim.x + threadIdx.x;
    if (i >= total4) return;
    float4 inv = *(const float4*)(g_inv + (i & 15) * 4);
    float4 v = ((float4*)out)[i];
    v.x *= inv.x; v.y *= inv.y; v.z *= inv.z; v.w *= inv.w;
    ((float4*)out)[i] = v;
}

extern "C" void kernel_launch(void* const* d_in, const int* in_sizes, int n_in,
                              void* d_out, int out_size) {
    const float* h = (const float*)d_in[0];
    const int* adj = (const int*)d_in[1];
    const float* amount = (const float*)d_in[2];
    const float* count = (const float*)d_in[3];
    const float* fc_w = (const float*)d_in[4];
    const float* fc_b = (const float*)d_in[5];
    float* out = (float*)d_out;

    int N = in_sizes[0] / FDIM;
    int E = in_sizes[2];

    k_init<<<1, 64>>>();
    k_wprep<<<(FDIM * TWOF + 255) / 256, 256>>>(fc_w);
    cudaMemsetAsync(d_out, 0, (size_t)out_size * sizeof(float));
    k_minmax<<<512, 256>>>(amount, count, E);
    k_gemm<<<(N + GN - 1) / GN, 128>>>(h, fc_b, N);
    k_edge<<<1184, 256>>>(amount, count, adj, h, out, E);
    k_inv<<<1, 64>>>();
    int total4 = out_size / 4;
    k_norm<<<(total4 + 255) / 256, 256>>>(out, total4);
}